// round 16
// baseline (speedup 1.0000x reference)
#include <cuda_runtime.h>
#include <cuda_bf16.h>
#include <math.h>
#include <stdint.h>

// Problem constants
#define XOUT_SIZE (16*12*128*128)
#define A_ROW 18720                 // one padded h2 row: 130 entries x 144 B

// Scratch (device globals — no cudaMalloc allowed)
__device__ __align__(16) char g_h2p[16*128*A_ROW];       // conv2 out, PADDED rows
__device__ __align__(16) uint32_t g_W1Fh[9*8*64];        // conv1 bf16 B-frags
__device__ __align__(16) uint32_t g_W2Fh[4*8*64];        // conv2 bf16 B-frags
__device__ __align__(16) uint32_t g_W3Bh[2*9*4608];      // [hh][tap][ih][kk][qq][576w]
__device__ float g_lad[16*256];                          // per-(image,row,half) partials
__device__ unsigned g_tick[16];                          // per-image tickets

// ---------------------------------------------------------------------------
// helpers
// ---------------------------------------------------------------------------
__device__ __forceinline__ uint32_t s2u(const void* p){
    uint32_t a;
    asm("{ .reg .u64 t; cvta.to.shared.u64 t, %1; cvt.u32.u64 %0, t; }" : "=r"(a) : "l"(p));
    return a;
}
__device__ __forceinline__ void cp16(uint32_t dst, const void* src, uint32_t sz){
    asm volatile("cp.async.cg.shared.global [%0], [%1], 16, %2;"
                 :: "r"(dst), "l"(src), "r"(sz) : "memory");
}
#define CP_COMMIT() asm volatile("cp.async.commit_group;" ::: "memory")

#define MBI(a,c)  asm volatile("mbarrier.init.shared.b64 [%0], %1;" :: "r"(a), "r"(c) : "memory")
#define METX(a,n) asm volatile("mbarrier.arrive.expect_tx.shared.b64 _, [%0], %1;" :: "r"(a), "r"(n) : "memory")
#define BULK_G2S(dst,src,sz,mb) \
    asm volatile("cp.async.bulk.shared::cluster.global.mbarrier::complete_tx::bytes [%0], [%1], %2, [%3];" \
                 :: "r"(dst), "l"(src), "r"(sz), "r"(mb) : "memory")

#define WAIT_PARITY(mbar, ph) do { \
    uint32_t _m=(uint32_t)(mbar), _p=(uint32_t)(ph), _d; \
    asm volatile("{\n\t.reg .pred p;\n\t" \
        "mbarrier.try_wait.parity.acquire.cta.shared::cta.b64 p, [%1], %2;\n\t" \
        "selp.b32 %0,1,0,p;\n\t}" : "=r"(_d) : "r"(_m), "r"(_p) : "memory"); \
    while(!_d){ \
        asm volatile("{\n\t.reg .pred p;\n\t" \
            "mbarrier.try_wait.parity.acquire.cta.shared::cta.b64 p, [%1], %2, 0x989680;\n\t" \
            "selp.b32 %0,1,0,p;\n\t}" : "=r"(_d) : "r"(_m), "r"(_p) : "memory"); } \
} while(0)

__device__ __forceinline__ void mma_bf16(float* d, uint32_t a0, uint32_t a1,
                                         uint32_t a2, uint32_t a3,
                                         uint32_t b0, uint32_t b1){
    asm volatile(
        "mma.sync.aligned.m16n8k16.row.col.f32.bf16.bf16.f32 "
        "{%0,%1,%2,%3}, {%4,%5,%6,%7}, {%8,%9}, {%0,%1,%2,%3};"
        : "+f"(d[0]), "+f"(d[1]), "+f"(d[2]), "+f"(d[3])
        : "r"(a0), "r"(a1), "r"(a2), "r"(a3), "r"(b0), "r"(b1));
}

__device__ __forceinline__ void ldsm4(uint32_t& r0, uint32_t& r1,
                                      uint32_t& r2, uint32_t& r3, uint32_t addr){
    asm volatile("ldmatrix.sync.aligned.m8n8.x4.shared.b16 {%0,%1,%2,%3}, [%4];"
        : "=r"(r0), "=r"(r1), "=r"(r2), "=r"(r3) : "r"(addr));
}

// ---------------------------------------------------------------------------
// k_trans: W1/W2 bf16 fragment packing + ticket reset.
// ---------------------------------------------------------------------------
__global__ void k_trans(const float* __restrict__ W1,
                        const float* __restrict__ W2) {
    int i = blockIdx.x * 256 + threadIdx.x;
    if (i < 16) g_tick[i] = 0u;
    if (i < 4608) {
        int tile = i >> 6; int l2 = i & 63;
        int tap = tile >> 3, nt = tile & 7;
        int lane = l2 >> 1, reg = l2 & 1;
        int oc  = nt*8 + (lane >> 2);
        int ic0 = 2*(lane & 3) + reg*8;
        __nv_bfloat162 w = __floats2bfloat162_rn(
            W1[oc*144 + ic0*9 + tap], W1[oc*144 + (ic0+1)*9 + tap]);
        g_W1Fh[i] = *(uint32_t*)&w;
    }
    int j = i - 4608;
    if (j >= 0 && j < 2048) {
        int tile = j >> 6; int l2 = j & 63;
        int kk = tile >> 3, nt = tile & 7;
        int lane = l2 >> 1, reg = l2 & 1;
        int oc  = nt*8 + (lane >> 2);
        int ic0 = kk*16 + 2*(lane & 3) + reg*8;
        __nv_bfloat162 w = __floats2bfloat162_rn(W2[oc*64 + ic0], W2[oc*64 + ic0 + 1]);
        g_W2Fh[j] = *(uint32_t*)&w;
    }
}

// ---------------------------------------------------------------------------
// Fused conv1+conv2 bf16 (validated R13/R14) + distributed W3 pack ([hh][tap])
// + PADDED h2 output rows (validated R15). 3 CTAs/SM.
// ---------------------------------------------------------------------------
#define Z_PITCH 48
#define A2_PITCH 144
#define B1_OFF 18720u
#define B2_OFF 37152u
#define SM12_BYTES 45344

__global__ void __launch_bounds__(256, 3) k_conv12(const float* __restrict__ x,
                                                   const float* __restrict__ cond,
                                                   const float* __restrict__ b1,
                                                   const float* __restrict__ b2,
                                                   const float* __restrict__ W3) {
    extern __shared__ float dyn[];
    __shared__ float s_b1[64], s_b2[64];

    int b  = blockIdx.y;
    int gr = blockIdx.x;
    int t  = threadIdx.x;
    int w = t >> 5, lane = t & 31;
    int g = lane >> 2, tig = lane & 3;
    int px0 = (w & 3) * 32;
    int nc0 = (w >> 2) * 32;
    int ntb = (w >> 2) * 4;
    int lanRow = (lane & 7) + ((lane >> 3) & 1) * 8;
    int lanCol = ((lane >> 4) & 1) * 16;

    char* sm = (char*)dyn;
    uint32_t smb = s2u(sm);

    // ---- distributed W3 fragment packing, [hh][tap][ih][kk][qq] order ----
    {
        int m = (b*128 + gr)*256 + t;
        if (m < 2*9*4608) {
            int hh  = m / 41472; int r1 = m - hh*41472;
            int tap = r1 / 4608; int r2 = r1 - tap*4608;
            int ih  = r2 / 2304; int r3 = r2 - ih*2304;
            int kk  = r3 / 1152; int r4a = r3 - kk*1152;
            int qq  = r4a / 576; int r4 = r4a - qq*576;
            int lne, reg, ntl;
            if (r4 < 512) {
                int pp = r4 >> 7; int ww = r4 & 127;
                lne = ww >> 2; int wsel = ww & 3;
                ntl = 2*pp + (wsel >> 1); reg = wsel & 1;
            } else {
                int r5 = r4 - 512;
                lne = r5 >> 1; reg = r5 & 1; ntl = 8;
            }
            int nt  = qq*9 + ntl;
            int n   = hh*144 + nt*8 + (lne >> 2);
            int ic0 = ih*32 + kk*16 + 2*(lne & 3) + reg*8;
            int c   = n / 24, s = n - c*24;
            float lo = 0.f, hi = 0.f;
            if (s < 23) {
                lo = W3[(c*23 + s)*576 + ic0*9 + tap];
                hi = W3[(c*23 + s)*576 + (ic0+1)*9 + tap];
            }
            __nv_bfloat162 wv = __floats2bfloat162_rn(lo, hi);
            g_W3Bh[m] = *(uint32_t*)&wv;
        }
    }

    if (t < 64)       s_b1[t] = b1[t];
    else if (t < 128) s_b2[t-64] = b2[t-64];

    for (int i = t; i < 1152; i += 256) cp16(smb + B1_OFF + (uint32_t)(i*16), g_W1Fh + i*4, 16u);
    for (int i = t; i < 512;  i += 256) cp16(smb + B2_OFF + (uint32_t)(i*16), g_W2Fh + i*4, 16u);
    CP_COMMIT();

    // build z tile bf16
    for (int i = t; i < 6240; i += 256) {
        int ch = i / 390; int slot = i - ch*390;
        int r = slot / 130; int pp = slot - r*130;
        int row = gr + r - 1, px = pp - 1;
        float v = 0.f;
        if ((unsigned)row < 128u && (unsigned)px < 128u) {
            if (ch < 12)
                v = ((row + px) & 1) ? x[((b*12 + ch) << 14) + (row << 7) + px] : 0.f;
            else
                v = cond[((b*4 + (ch-12)) << 14) + (row << 7) + px];
        }
        *(__nv_bfloat16*)(sm + slot*Z_PITCH + ch*2) = __float2bfloat16(v);
    }
    asm volatile("cp.async.wait_group 0;" ::: "memory");
    __syncthreads();

    // ---- phase 1: conv1 ----
    float d1[32];
    #pragma unroll
    for (int i = 0; i < 32; i++) d1[i] = 0.f;

    #pragma unroll
    for (int tap = 0; tap < 9; tap++) {
        int kh = tap / 3;
        int dw = tap - kh*3 - 1;
        uint32_t A0[4], A1[4];
        uint32_t a0addr = smb + (uint32_t)((kh*130 + 1 + dw + px0 + lanRow)*Z_PITCH + lanCol);
        ldsm4(A0[0], A0[1], A0[2], A0[3], a0addr);
        ldsm4(A1[0], A1[1], A1[2], A1[3], a0addr + 16u*Z_PITCH);
        const uint32_t* bB = (const uint32_t*)(sm + B1_OFF) + (tap*8 + ntb)*64 + lane*2;
        #pragma unroll
        for (int ntl = 0; ntl < 4; ntl++) {
            uint2 bb = *(const uint2*)(bB + ntl*64);
            mma_bf16(&d1[ntl*8],     A0[0], A0[1], A0[2], A0[3], bb.x, bb.y);
            mma_bf16(&d1[ntl*8 + 4], A1[0], A1[1], A1[2], A1[3], bb.x, bb.y);
        }
    }

    __syncthreads();
    #pragma unroll
    for (int mm = 0; mm < 2; mm++) {
        int row = px0 + mm*16 + g;
        #pragma unroll
        for (int ntl = 0; ntl < 4; ntl++) {
            int col = nc0 + ntl*8 + 2*tig;
            float bb0 = s_b1[col], bb1 = s_b1[col+1];
            __nv_bfloat162 v0 = __floats2bfloat162_rn(
                fmaxf(d1[ntl*8+mm*4+0] + bb0, 0.f), fmaxf(d1[ntl*8+mm*4+1] + bb1, 0.f));
            __nv_bfloat162 v1 = __floats2bfloat162_rn(
                fmaxf(d1[ntl*8+mm*4+2] + bb0, 0.f), fmaxf(d1[ntl*8+mm*4+3] + bb1, 0.f));
            *(uint32_t*)(sm +  row     *A2_PITCH + col*2) = *(uint32_t*)&v0;
            *(uint32_t*)(sm + (row + 8)*A2_PITCH + col*2) = *(uint32_t*)&v1;
        }
    }
    __syncthreads();

    // ---- phase 2: conv2 ----
    float d2[32];
    #pragma unroll
    for (int i = 0; i < 32; i++) d2[i] = 0.f;

    #pragma unroll
    for (int kk = 0; kk < 4; kk++) {
        uint32_t A0[4], A1[4];
        uint32_t aaddr = smb + (uint32_t)((px0 + lanRow)*A2_PITCH + kk*32 + lanCol);
        ldsm4(A0[0], A0[1], A0[2], A0[3], aaddr);
        ldsm4(A1[0], A1[1], A1[2], A1[3], aaddr + 16u*A2_PITCH);
        const uint32_t* bB = (const uint32_t*)(sm + B2_OFF) + (kk*8 + ntb)*64 + lane*2;
        #pragma unroll
        for (int ntl = 0; ntl < 4; ntl++) {
            uint2 bb = *(const uint2*)(bB + ntl*64);
            mma_bf16(&d2[ntl*8],     A0[0], A0[1], A0[2], A0[3], bb.x, bb.y);
            mma_bf16(&d2[ntl*8 + 4], A1[0], A1[1], A1[2], A1[3], bb.x, bb.y);
        }
    }

    // epilogue 2: relu+bias -> PADDED bf16 staging -> gmem
    __syncthreads();
    if (t < 9)            *(uint4*)(sm + t*16) = make_uint4(0,0,0,0);
    else if (t < 18)      *(uint4*)(sm + 18576 + (t-9)*16) = make_uint4(0,0,0,0);
    #pragma unroll
    for (int mm = 0; mm < 2; mm++) {
        int row = px0 + mm*16 + g;
        #pragma unroll
        for (int ntl = 0; ntl < 4; ntl++) {
            int col = nc0 + ntl*8 + 2*tig;
            float bb0 = s_b2[col], bb1 = s_b2[col+1];
            __nv_bfloat162 h0 = __floats2bfloat162_rn(
                fmaxf(d2[ntl*8+mm*4+0] + bb0, 0.f), fmaxf(d2[ntl*8+mm*4+1] + bb1, 0.f));
            __nv_bfloat162 h1v = __floats2bfloat162_rn(
                fmaxf(d2[ntl*8+mm*4+2] + bb0, 0.f), fmaxf(d2[ntl*8+mm*4+3] + bb1, 0.f));
            *(uint32_t*)(sm + (row + 1)*144 + col*2) = *(uint32_t*)&h0;
            *(uint32_t*)(sm + (row + 9)*144 + col*2) = *(uint32_t*)&h1v;
        }
    }
    __syncthreads();
    {
        const uint4* s4 = (const uint4*)sm;
        uint4* dst = (uint4*)(g_h2p + (size_t)(b*128 + gr) * A_ROW);
        for (int i = t; i < 1170; i += 256) dst[i] = s4[i];
    }
}

// ---------------------------------------------------------------------------
// RQS spline (validated R1)
// ---------------------------------------------------------------------------
__device__ __forceinline__ float rqs_eval(const float* p, float xa, float& lad) {
    bool inside = (xa >= -3.f) && (xa <= 3.f);
    float xc = fminf(fmaxf(xa, -3.f), 3.f);

    float mw = p[0], mh = p[8];
    #pragma unroll
    for (int k = 1; k < 8; k++) { mw = fmaxf(mw, p[k]); mh = fmaxf(mh, p[8+k]); }
    float ew[8], eh[8]; float sw = 0.f, sh = 0.f;
    #pragma unroll
    for (int k = 0; k < 8; k++) {
        ew[k] = expf(p[k] - mw);   sw += ew[k];
        eh[k] = expf(p[8+k] - mh); sh += eh[k];
    }
    float rw = (1.f - 0.008f) / sw;
    float rh = (1.f - 0.008f) / sh;

    float sp[7];
    #pragma unroll
    for (int k = 0; k < 7; k++) {
        float u = p[16 + k];
        sp[k] = (u > 15.f) ? u : log1pf(expf(u));
    }

    float cw = -3.f, ch = -3.f, cumw = 0.f, cumh = 0.f, dprev = 1.f;
    float icw = -3.f, iw = 1.f, ich = -3.f, ih = 1.f, id0 = 1.f, id1 = 1.f;
    #pragma unroll
    for (int k = 0; k < 8; k++) {
        cumw += 0.001f + ew[k]*rw;
        cumh += 0.001f + eh[k]*rh;
        float cwn = (k == 7) ? 3.f : fmaf(6.f, cumw, -3.f);
        float chn = (k == 7) ? 3.f : fmaf(6.f, cumh, -3.f);
        float dn  = (k == 7) ? 1.f : (0.001f + sp[k]);
        if (xc >= cw) { icw = cw; iw = cwn - cw; ich = ch; ih = chn - ch; id0 = dprev; id1 = dn; }
        cw = cwn; ch = chn; dprev = dn;
    }

    float riw   = 1.f / iw;
    float delta = ih * riw;
    float theta = (xc - icw) * riw;
    float omt = 1.f - theta;
    float t1  = theta * omt;
    float th2 = theta * theta;
    float num = ih * (delta*th2 + id0*t1);
    float den = delta + (id0 + id1 - 2.f*delta)*t1;
    float y   = ich + num / den;
    float dnum = delta*delta*(id1*th2 + 2.f*delta*t1 + id0*omt*omt);
    float l = logf(dnum) - 2.f*logf(den);

    lad = inside ? l : 0.f;
    return inside ? y : xa;
}

// ---------------------------------------------------------------------------
// conv3 bf16 MMA: ALL-RESIDENT smem (A 56160 + 9 B tap slots 165888 =
// 222048 B), 1 CTA/SM, 512 threads = 16 warps (warp = 16 px x N-quarter).
// All loads issued up-front on per-tap mbarriers; ZERO mainloop barriers.
// ---------------------------------------------------------------------------
#define A_BYTES 56160u
#define TSLOT 18432u
#define SM3_BYTES (56160 + 9*18432)   // 222,048

__global__ void __launch_bounds__(512, 1) k_conv3_mma(const float* __restrict__ x,
                                                      const float* __restrict__ logdet_in,
                                                      const float* __restrict__ b3,
                                                      float* __restrict__ out) {
    extern __shared__ float dyn[];
    __shared__ __align__(8) uint64_t s_mbar[10];   // [0]=A, [1..9]=taps
    __shared__ float s_b3[276];
    __shared__ float s_red[16];
    __shared__ unsigned s_last;

    int b  = blockIdx.y;
    int bx = blockIdx.x;
    int gr = bx >> 1;
    int hh = bx & 1;
    int t  = threadIdx.x;
    int w = t >> 5, lane = t & 31;
    int g = lane >> 2, tig = lane & 3;
    int px0 = (w & 7) * 16;      // one m16 tile per warp
    int qq  = w >> 3;            // N quarter

    char* sA = (char*)dyn;
    uint32_t sAu = s2u(sA);
    uint32_t baseB = sAu + A_BYTES;
    uint32_t mA = s2u(&s_mbar[0]);

    for (int i = t; i < 276; i += 512) s_b3[i] = b3[i];

    if (t == 0) {
        #pragma unroll
        for (int i = 0; i < 10; i++) MBI(s2u(&s_mbar[i]), 1);
    }
    __syncthreads();

    // issue ALL loads up-front: A rows + all 9 B taps
    int nvalid = 3 - (gr == 0) - (gr == 127);
    if (t == 0) {
        METX(mA, (uint32_t)(nvalid * A_ROW));
        #pragma unroll
        for (int r = 0; r < 3; r++) {
            int row = gr + r - 1;
            if ((unsigned)row < 128u)
                BULK_G2S(sAu + (uint32_t)(r * A_ROW),
                         g_h2p + (size_t)(b*128 + row) * A_ROW,
                         (uint32_t)A_ROW, mA);
        }
        #pragma unroll
        for (int tp = 0; tp < 9; tp++) {
            uint32_t mB = s2u(&s_mbar[1 + tp]);
            METX(mB, TSLOT);
            BULK_G2S(baseB + (uint32_t)tp * TSLOT,
                     (const char*)g_W3Bh + (size_t)(hh*9 + tp) * TSLOT,
                     TSLOT, mB);
        }
    }
    // OOB edge rows zero-filled by STS
    if (gr == 0) {
        uint4* z = (uint4*)sA;
        for (int i = t; i < 1170; i += 512) z[i] = make_uint4(0,0,0,0);
    } else if (gr == 127) {
        uint4* z = (uint4*)(sA + 2*A_ROW);
        for (int i = t; i < 1170; i += 512) z[i] = make_uint4(0,0,0,0);
    }
    __syncthreads();           // STS zero-fill visible to all warps
    WAIT_PARITY(mA, 0u);       // A resident (per-warp wait; no CTA barrier)

    float d[36];
    #pragma unroll
    for (int i = 0; i < 36; i++) d[i] = 0.f;

    uint32_t aBase = sAu
        + (uint32_t)((1 + px0 + (lane & 7) + ((lane >> 3) & 1)*8) * 144
                     + ((lane >> 4) & 1)*16);

    // barrier-free mainloop: each warp waits only on its tap's mbarrier
    for (int tp = 0; tp < 9; tp++) {
        WAIT_PARITY(s2u(&s_mbar[1 + tp]), 0u);

        int kh = tp / 3;
        int dw = tp - kh*3 - 1;
        uint32_t aTap = aBase + (uint32_t)(kh*A_ROW + dw*144);
        const char* sBq = (const char*)dyn + A_BYTES + (size_t)tp*TSLOT
                          + (size_t)qq * 2304;

        #pragma unroll
        for (int ih = 0; ih < 2; ih++) {
            #pragma unroll
            for (int kk = 0; kk < 2; kk++) {
                uint32_t A0[4];
                ldsm4(A0[0], A0[1], A0[2], A0[3],
                      aTap + (uint32_t)(ih*64 + kk*32));
                const char* bp = sBq + (size_t)ih*9216 + (size_t)kk*4608;
                #pragma unroll
                for (int pp = 0; pp < 4; pp++) {
                    uint4 bb = *(const uint4*)(bp + pp*512 + lane*16);
                    int n0 = pp*8;
                    mma_bf16(&d[n0],     A0[0], A0[1], A0[2], A0[3], bb.x, bb.y);
                    mma_bf16(&d[n0 + 4], A0[0], A0[1], A0[2], A0[3], bb.z, bb.w);
                }
                uint2 b8 = *(const uint2*)(bp + 2048 + lane*8);
                mma_bf16(&d[32], A0[0], A0[1], A0[2], A0[3], b8.x, b8.y);
            }
        }
    }

    // epilogue: accumulators -> sD (reuses A + tap0 region) -> spline
    __syncthreads();
    {
        float* sD = dyn;
        int row0 = px0 + g;
        #pragma unroll
        for (int nt = 0; nt < 9; nt++) {
            int col = qq*72 + nt*8 + 2*tig;
            sD[ row0      * 145 + col    ] = d[nt*4 + 0];
            sD[ row0      * 145 + col + 1] = d[nt*4 + 1];
            sD[(row0 + 8) * 145 + col    ] = d[nt*4 + 2];
            sD[(row0 + 8) * 145 + col + 1] = d[nt*4 + 3];
        }
    }
    __syncthreads();

    float ladsum = 0.f;
    if (t < 384) {
        const float* sD = dyn;
        int px = t & 127;
        int clbase = (t >> 7) * 2;
        int par = (gr + px) & 1;
        #pragma unroll
        for (int cc = 0; cc < 2; cc++) {
            int cl = clbase + cc;
            int c  = hh*6 + cl;
            float p[23];
            #pragma unroll
            for (int sidx = 0; sidx < 23; sidx++)
                p[sidx] = sD[px*145 + cl*24 + sidx] + s_b3[c*23 + sidx];

            size_t xbase = (((size_t)(b*12 + c)) << 14) + ((size_t)gr << 7) + px;
            float xv = x[xbase];
            float xa = par ? 0.f : xv;
            float xf = par ? xv : 0.f;
            float lad;
            float y = rqs_eval(p, xa, lad);
            out[xbase] = xf + y;
            ladsum += lad;
        }
    }
    #pragma unroll
    for (int o = 16; o > 0; o >>= 1)
        ladsum += __shfl_down_sync(0xffffffffu, ladsum, o);
    if (lane == 0) s_red[w] = ladsum;
    __syncthreads();
    if (t == 0) {
        float v = 0.f;
        #pragma unroll
        for (int i = 0; i < 16; i++) v += s_red[i];
        g_lad[b*256 + bx] = v;
        __threadfence();
        unsigned old = atomicAdd(&g_tick[b], 1u);
        s_last = (old == 255u) ? 1u : 0u;
    }
    __syncthreads();

    if (s_last && w == 0) {
        __threadfence();
        float v = 0.f;
        #pragma unroll
        for (int i = 0; i < 8; i++) v += g_lad[b*256 + i*32 + lane];
        #pragma unroll
        for (int o = 16; o > 0; o >>= 1)
            v += __shfl_down_sync(0xffffffffu, v, o);
        if (lane == 0) out[XOUT_SIZE + b] = logdet_in[b] + v;
    }
}

// ---------------------------------------------------------------------------
extern "C" void kernel_launch(void* const* d_in, const int* in_sizes, int n_in,
                              void* d_out, int out_size) {
    const float* x      = (const float*)d_in[0];
    const float* logdet = (const float*)d_in[1];
    const float* cond   = (const float*)d_in[2];
    const float* W1     = (const float*)d_in[3];
    const float* b1     = (const float*)d_in[4];
    const float* W2     = (const float*)d_in[5];
    const float* b2     = (const float*)d_in[6];
    const float* W3     = (const float*)d_in[7];
    const float* b3     = (const float*)d_in[8];
    float* out = (float*)d_out;

    cudaFuncSetAttribute(k_conv12, cudaFuncAttributeMaxDynamicSharedMemorySize, SM12_BYTES);
    cudaFuncSetAttribute(k_conv3_mma, cudaFuncAttributeMaxDynamicSharedMemorySize, SM3_BYTES);

    k_trans<<<26, 256>>>(W1, W2);
    k_conv12<<<dim3(128, 16), 256, SM12_BYTES>>>(x, cond, b1, b2, W3);
    k_conv3_mma<<<dim3(256, 16), 512, SM3_BYTES>>>(x, logdet, b3, out);
}